// round 14
// baseline (speedup 1.0000x reference)
#include <cuda_runtime.h>
#include <cuda_fp16.h>
#include <cstdint>

// ===========================================================================
// Model_86011015070455 — R14: 5-stage cp.async ring with SINGLE sync/chunk
//   (write-stage never collides with compute-stage at distance-3 mod 5),
//   init folded into convert_x. Math identical to R13.
// ===========================================================================

__device__ __forceinline__ uint32_t smem_u32(const void* p) {
    uint32_t a;
    asm("{ .reg .u64 t; cvta.to.shared.u64 t, %1; cvt.u32.u64 %0, t; }" : "=r"(a) : "l"(p));
    return a;
}
__device__ __forceinline__ void ldsm4(uint32_t& r0, uint32_t& r1, uint32_t& r2, uint32_t& r3,
                                      uint32_t addr) {
    asm volatile("ldmatrix.sync.aligned.m8n8.x4.shared.b16 {%0,%1,%2,%3}, [%4];"
                 : "=r"(r0), "=r"(r1), "=r"(r2), "=r"(r3) : "r"(addr));
}
__device__ __forceinline__ void mma16816(float* d, const uint32_t* a, const uint32_t* b) {
    asm volatile("mma.sync.aligned.m16n8k16.row.col.f32.f16.f16.f32 "
                 "{%0,%1,%2,%3}, {%4,%5,%6,%7}, {%8,%9}, {%0,%1,%2,%3};"
                 : "+f"(d[0]), "+f"(d[1]), "+f"(d[2]), "+f"(d[3])
                 : "r"(a[0]), "r"(a[1]), "r"(a[2]), "r"(a[3]), "r"(b[0]), "r"(b[1]));
}
__device__ __forceinline__ void cp16(uint32_t dst, const void* src) {
    asm volatile("cp.async.cg.shared.global [%0], [%1], 16;"
                 :: "r"(dst), "l"(__cvta_generic_to_global(src)));
}
#define CP_COMMIT() asm volatile("cp.async.commit_group;")
#define CP_WAIT2()  asm volatile("cp.async.wait_group 2;")
#define CP_WAIT0()  asm volatile("cp.async.wait_group 0;")
#define SWZ64(o) ((o) ^ (((o) >> 3) & 0x30))

__device__ __forceinline__ uint32_t packh2(__half a, __half b) {
    __half2 t = __halves2half2(a, b);
    return *(uint32_t*)&t;
}
__device__ __forceinline__ uint32_t haddrelu2(uint32_t a, uint32_t b) {
    __half2 s = __hadd2(*(__half2*)&a, *(__half2*)&b);
    s = __hmax2(s, __float2half2_rn(0.f));
    return *(uint32_t*)&s;
}

// ------------------------------------------------------------- device scratch
__device__ __half g_A1h[4096 * 1024];
__device__ __half g_B1h[4096 * 1024];
__device__ __half g_T1h[4096 * 1024];
__device__ float  g_erow[4096];
__device__ float  g_eint[131072];
__device__ __half g_T2T[1024 * 1024];
__device__ __half g_I2T[1024 * 1024];
__device__ __half g_Xh[4096 * 416];
__device__ __half g_W1T[3072 * 416];

// ------------------------------------------- prep: W2 transpose to fp16
__global__ void prep_transpose(const float* __restrict__ t2w, const float* __restrict__ i2w) {
    __shared__ float tile[32][33];
    const float* src = blockIdx.z ? i2w : t2w;
    __half* dst = blockIdx.z ? g_I2T : g_T2T;
    int k = blockIdx.y * 32 + threadIdx.y;
    int n = blockIdx.x * 32 + threadIdx.x;
    tile[threadIdx.y][threadIdx.x] = src[k * 1024 + n];
    __syncthreads();
    float v = tile[threadIdx.x][threadIdx.y];
    int nn = blockIdx.x * 32 + threadIdx.y;
    int kk = blockIdx.y * 32 + threadIdx.x;
    dst[nn * 1024 + kk] = __float2half_rn(v);
}

// ------------- prep: x rows -> fp16 (K padded to 416) + zero-init outputs ---
__global__ void convert_x_kernel(const float* __restrict__ x) {
    const int gid = blockIdx.x * 128 + threadIdx.x;
    if (gid < 131072) g_eint[gid] = 0.f;
    if (gid < 4096)   g_erow[gid] = 0.f;
    const int row = blockIdx.x;
    const int t = threadIdx.x;
    if (t >= 104) return;
    const int k = t * 4;
    uint2 out;
    if (k < 400) {
        float4 v = *(const float4*)(x + (size_t)row * 400 + k);
        out = make_uint2(packh2(__float2half_rn(v.x), __float2half_rn(v.y)),
                         packh2(__float2half_rn(v.z), __float2half_rn(v.w)));
    } else {
        out = make_uint2(0u, 0u);
    }
    *(uint2*)&g_Xh[(size_t)row * 416 + k] = out;
}

// --------------------- prep: W1 segments -> transposed fp16 [3072][416] -----
__global__ void convert_w1_kernel(const float* __restrict__ t1w,
                                  const float* __restrict__ i1w) {
    __shared__ float tile[32][33];
    int n = blockIdx.x * 32 + threadIdx.x;
    int k = blockIdx.y * 32 + threadIdx.y;
    float v = 0.f;
    if (k < 400) {
        int seg = n >> 10, nc = n & 1023;
        v = (seg == 0) ? t1w[k * 1024 + nc]
          : (seg == 1) ? i1w[k * 1024 + nc]
                       : i1w[(k + 400) * 1024 + nc];
    }
    tile[threadIdx.y][threadIdx.x] = v;
    __syncthreads();
    int nn = blockIdx.x * 32 + threadIdx.y;
    int kk = blockIdx.y * 32 + threadIdx.x;
    g_W1T[(size_t)nn * 416 + kk] = __float2half_rn(tile[threadIdx.x][threadIdx.y]);
}

// --------------------------------------------- shared GEMM tile constants ---
static constexpr uint32_t TB_A = 0;
static constexpr uint32_t TB_B = 8 * 1024;
static constexpr uint32_t TB_STAGE = 16 * 1024;
static constexpr int NSTAGE = 5;
static constexpr uint32_t TS_SMEM = NSTAGE * TB_STAGE + 1024 + 1024;

// ------------------------------------- stage1 GEMM (HMMA): X @ W1 -> 3 segs -
static constexpr int NCH1 = 13;

__global__ __launch_bounds__(128, 2)
void stage1_mma_kernel(const float* __restrict__ t1b, const float* __restrict__ i1b)
{
    extern __shared__ char smem_raw[];
    const uint32_t smem_u = smem_u32(smem_raw);
    const uint32_t base_u = (smem_u + 1023) & ~1023u;
    char* p = smem_raw + (base_u - smem_u);
    float* sb1 = (float*)(p + NSTAGE * TB_STAGE);

    const int tid  = threadIdx.x;
    const int lane = tid & 31;
    const int wid  = tid >> 5;
    const int wm   = wid & 1;
    const int wn   = wid >> 1;
    const int m0   = blockIdx.x * 128;
    const int n0   = blockIdx.y * 128;
    const int seg  = n0 >> 10;

    if (seg == 0)      sb1[tid] = t1b[n0 + tid];
    else if (seg == 1) sb1[tid] = i1b[n0 - 1024 + tid];
    else               sb1[tid] = 0.f;

    auto fillAB = [&](int stage, int k0) {
        const uint32_t sb = base_u + (uint32_t)stage * TB_STAGE;
        #pragma unroll
        for (int t = 0; t < 4; ++t) {
            int idx = tid + t * 128;
            int rl = idx >> 2;
            int cc = idx & 3;
            const __half* src = g_Xh + (size_t)(m0 + rl) * 416 + k0 + cc * 8;
            cp16(sb + TB_A + SWZ64((uint32_t)(rl * 64 + cc * 16)), src);
        }
        #pragma unroll
        for (int t = 0; t < 4; ++t) {
            int idx = tid + t * 128;
            int rl = idx >> 2;
            int cc = idx & 3;
            const __half* src = g_W1T + (size_t)(n0 + rl) * 416 + k0 + cc * 8;
            cp16(sb + TB_B + SWZ64((uint32_t)(rl * 64 + cc * 16)), src);
        }
    };

    uint32_t aoff[4], boff[4];
    #pragma unroll
    for (int mf = 0; mf < 4; ++mf)
        aoff[mf] = (uint32_t)((wm * 64 + mf * 16 + (lane & 15)) * 64 + (lane >> 4) * 16);
    #pragma unroll
    for (int nf2 = 0; nf2 < 4; ++nf2)
        boff[nf2] = (uint32_t)((wn * 64 + nf2 * 16 + (lane & 7) + ((lane & 16) ? 8 : 0)) * 64
                               + ((lane >> 3) & 1) * 16);

    float acc[4][8][4];
    #pragma unroll
    for (int mf = 0; mf < 4; ++mf)
        #pragma unroll
        for (int nf = 0; nf < 8; ++nf)
            #pragma unroll
            for (int q = 0; q < 4; ++q) acc[mf][nf][q] = 0.f;

    auto compute = [&](int stage) {
        const uint32_t sb = base_u + (uint32_t)stage * TB_STAGE;
        #pragma unroll
        for (int kf = 0; kf < 2; ++kf) {
            const uint32_t kadd = kf * 32;
            uint32_t ah[4][4], bf[8][2];
            #pragma unroll
            for (int mf = 0; mf < 4; ++mf) {
                uint32_t sw = SWZ64(aoff[mf] + kadd);
                ldsm4(ah[mf][0], ah[mf][1], ah[mf][2], ah[mf][3], sb + TB_A + sw);
            }
            #pragma unroll
            for (int nf2 = 0; nf2 < 4; ++nf2) {
                uint32_t sw = SWZ64(boff[nf2] + kadd);
                ldsm4(bf[nf2 * 2][0], bf[nf2 * 2][1],
                      bf[nf2 * 2 + 1][0], bf[nf2 * 2 + 1][1], sb + TB_B + sw);
            }
            #pragma unroll
            for (int mf = 0; mf < 4; ++mf)
                #pragma unroll
                for (int nf = 0; nf < 8; ++nf)
                    mma16816(acc[mf][nf], ah[mf], bf[nf]);
        }
    };

    fillAB(0, 0);  CP_COMMIT();
    fillAB(1, 32); CP_COMMIT();
    fillAB(2, 64); CP_COMMIT();

    #pragma unroll 1
    for (int c = 0; c < NCH1; ++c) {
        if (c + 3 < NCH1) {
            fillAB((c + 3) % NSTAGE, (c + 3) * 32); CP_COMMIT();
            CP_WAIT2();
        } else {
            CP_WAIT0();
        }
        __syncthreads();
        compute(c % NSTAGE);
    }

    const int colBase = n0 & 1023;
    #pragma unroll
    for (int mf = 0; mf < 4; ++mf) {
        #pragma unroll
        for (int h = 0; h < 2; ++h) {
            const int m = m0 + wm * 64 + mf * 16 + (lane >> 2) + h * 8;
            #pragma unroll
            for (int nf = 0; nf < 8; ++nf) {
                const int nl = wn * 64 + nf * 8 + 2 * (lane & 3);
                float d0 = acc[mf][nf][h * 2 + 0] + sb1[nl];
                float d1 = acc[mf][nf][h * 2 + 1] + sb1[nl + 1];
                const size_t o = (size_t)m * 1024 + colBase + nl;
                if (seg == 0) {
                    d0 = fmaxf(d0, 0.f); d1 = fmaxf(d1, 0.f);
                    *(uint32_t*)&g_T1h[o] = packh2(__float2half_rn(d0), __float2half_rn(d1));
                } else if (seg == 1) {
                    *(uint32_t*)&g_A1h[o] = packh2(__float2half_rn(d0), __float2half_rn(d1));
                } else {
                    *(uint32_t*)&g_B1h[o] = packh2(__float2half_rn(d0), __float2half_rn(d1));
                }
            }
        }
    }
}

// --------------------------------------------- unified tensor stage (HMMA)
// 5-stage ring, single __syncthreads per chunk. bx<8192: interaction (A built
// on the fly from L2-resident A1h/B1h); bx>=8192: traj (A cp.async from T1h).
static constexpr int NCH = 32;

__global__ __launch_bounds__(128, 2)
void tensor_stage_kernel(const float* __restrict__ t2b, const float* __restrict__ t3w,
                         const float* __restrict__ i2b, const float* __restrict__ i3w)
{
    extern __shared__ char smem_raw[];
    const uint32_t smem_u = smem_u32(smem_raw);
    const uint32_t base_u = (smem_u + 1023) & ~1023u;
    char* p = smem_raw + (base_u - smem_u);

    float* sb2 = (float*)(p + NSTAGE * TB_STAGE);
    float* sw3 = sb2 + 128;

    const int tid  = threadIdx.x;
    const int lane = tid & 31;
    const int wid  = tid >> 5;
    const int wm   = wid & 1;
    const int wn   = wid >> 1;

    const bool traj = (blockIdx.x >= 8192);
    const int idx   = traj ? (blockIdx.x - 8192) : blockIdx.x;
    const int m0    = (idx >> 3) * 128;
    const int n0    = (idx & 7) * 128;

    const __half* WT  = traj ? g_T2T : g_I2T;
    const float*  b2g = traj ? t2b : i2b;
    const float*  w3g = traj ? t3w : i3w;
    float* eout       = traj ? g_erow : g_eint;

    sb2[tid] = b2g[n0 + tid];
    sw3[tid] = w3g[n0 + tid];

    const int rowA_base = (m0 >> 10) * 32 + ((m0 >> 5) & 31);
    const int rowB_base = (m0 >> 10) * 32;

    auto fillB = [&](int stage, int k0) {
        const uint32_t sb = base_u + (uint32_t)stage * TB_STAGE;
        #pragma unroll
        for (int t = 0; t < 4; ++t) {
            int idx2 = tid + t * 128;
            int rl = idx2 >> 2;
            int cc = idx2 & 3;
            const __half* src = WT + (size_t)(n0 + rl) * 1024 + k0 + cc * 8;
            cp16(sb + TB_B + SWZ64((uint32_t)(rl * 64 + cc * 16)), src);
        }
    };
    auto fillA_traj = [&](int stage, int k0) {
        const uint32_t sb = base_u + (uint32_t)stage * TB_STAGE;
        #pragma unroll
        for (int t = 0; t < 4; ++t) {
            int idx2 = tid + t * 128;
            int rl = idx2 >> 2;
            int cc = idx2 & 3;
            const __half* src = g_T1h + (size_t)(m0 + rl) * 1024 + k0 + cc * 8;
            cp16(sb + TB_A + SWZ64((uint32_t)(rl * 64 + cc * 16)), src);
        }
    };

    uint4 va[4], vb[4];
    auto ldA_int = [&](int k0) {
        #pragma unroll
        for (int t = 0; t < 4; ++t) {
            int idx2 = tid + t * 128;
            int rl = idx2 >> 2;
            int cc = idx2 & 3;
            int ra = rowA_base + (rl >> 5);
            int rb = rowB_base + (rl & 31);
            va[t] = *(const uint4*)&g_A1h[(size_t)ra * 1024 + k0 + cc * 8];
            vb[t] = *(const uint4*)&g_B1h[(size_t)rb * 1024 + k0 + cc * 8];
        }
    };
    auto stA_int = [&](int stage) {
        #pragma unroll
        for (int t = 0; t < 4; ++t) {
            int idx2 = tid + t * 128;
            int rl = idx2 >> 2;
            int cc = idx2 & 3;
            uint4 o;
            o.x = haddrelu2(va[t].x, vb[t].x);
            o.y = haddrelu2(va[t].y, vb[t].y);
            o.z = haddrelu2(va[t].z, vb[t].z);
            o.w = haddrelu2(va[t].w, vb[t].w);
            *(uint4*)(p + (uint32_t)stage * TB_STAGE + TB_A
                      + SWZ64((uint32_t)(rl * 64 + cc * 16))) = o;
        }
    };

    uint32_t aoff[4], boff[4];
    #pragma unroll
    for (int mf = 0; mf < 4; ++mf)
        aoff[mf] = (uint32_t)((wm * 64 + mf * 16 + (lane & 15)) * 64 + (lane >> 4) * 16);
    #pragma unroll
    for (int nf2 = 0; nf2 < 4; ++nf2)
        boff[nf2] = (uint32_t)((wn * 64 + nf2 * 16 + (lane & 7) + ((lane & 16) ? 8 : 0)) * 64
                               + ((lane >> 3) & 1) * 16);

    float acc[4][8][4];
    #pragma unroll
    for (int mf = 0; mf < 4; ++mf)
        #pragma unroll
        for (int nf = 0; nf < 8; ++nf)
            #pragma unroll
            for (int q = 0; q < 4; ++q) acc[mf][nf][q] = 0.f;

    auto compute = [&](int stage) {
        const uint32_t sb = base_u + (uint32_t)stage * TB_STAGE;
        #pragma unroll
        for (int kf = 0; kf < 2; ++kf) {
            const uint32_t kadd = kf * 32;
            uint32_t ah[4][4], bf[8][2];
            #pragma unroll
            for (int mf = 0; mf < 4; ++mf) {
                uint32_t sw = SWZ64(aoff[mf] + kadd);
                ldsm4(ah[mf][0], ah[mf][1], ah[mf][2], ah[mf][3], sb + TB_A + sw);
            }
            #pragma unroll
            for (int nf2 = 0; nf2 < 4; ++nf2) {
                uint32_t sw = SWZ64(boff[nf2] + kadd);
                ldsm4(bf[nf2 * 2][0], bf[nf2 * 2][1],
                      bf[nf2 * 2 + 1][0], bf[nf2 * 2 + 1][1], sb + TB_B + sw);
            }
            #pragma unroll
            for (int mf = 0; mf < 4; ++mf)
                #pragma unroll
                for (int nf = 0; nf < 8; ++nf)
                    mma16816(acc[mf][nf], ah[mf], bf[nf]);
        }
    };

    // ---- prologue: fill stages 0..2 ----
    fillB(0, 0);  if (traj) fillA_traj(0, 0);  CP_COMMIT();
    fillB(1, 32); if (traj) fillA_traj(1, 32); CP_COMMIT();
    fillB(2, 64); if (traj) fillA_traj(2, 64); CP_COMMIT();
    if (!traj) { ldA_int(0); stA_int(0); }

    #pragma unroll 1
    for (int c = 0; c < NCH; ++c) {
        if (c + 3 < NCH) {
            fillB((c + 3) % NSTAGE, (c + 3) * 32);
            if (traj) fillA_traj((c + 3) % NSTAGE, (c + 3) * 32);
            CP_COMMIT();
        }
        if (!traj && c + 1 < NCH) ldA_int((c + 1) * 32);
        if (c + 3 < NCH) CP_WAIT2(); else CP_WAIT0();
        __syncthreads();
        compute(c % NSTAGE);
        if (!traj && c + 1 < NCH) stA_int((c + 1) % NSTAGE);
    }

    // ---- epilogue: fused layer-3  e_m += sum_n w3[n]*relu(D+b2[n]) ----
    #pragma unroll
    for (int mf = 0; mf < 4; ++mf) {
        #pragma unroll
        for (int h = 0; h < 2; ++h) {
            float s = 0.f;
            #pragma unroll
            for (int nf = 0; nf < 8; ++nf) {
                int nl = wn * 64 + nf * 8 + 2 * (lane & 3);
                float d0 = acc[mf][nf][h * 2 + 0];
                float d1 = acc[mf][nf][h * 2 + 1];
                s += fmaxf(d0 + sb2[nl], 0.f) * sw3[nl]
                   + fmaxf(d1 + sb2[nl + 1], 0.f) * sw3[nl + 1];
            }
            s += __shfl_xor_sync(0xffffffffu, s, 1);
            s += __shfl_xor_sync(0xffffffffu, s, 2);
            if ((lane & 3) == 0) {
                int m = m0 + wm * 64 + mf * 16 + (lane >> 2) + h * 8;
                atomicAdd(&eout[m], s);
            }
        }
    }
}

// ------------------------------------------------------------------ finalize
__global__ void finalize_kernel(const float* __restrict__ edges,
                                const float* __restrict__ t3b,
                                const float* __restrict__ i3b,
                                float* __restrict__ out)
{
    const int b = blockIdx.x;
    const int tid = threadIdx.x;
    const float bias_i = i3b[0];

    float s = 0.f;
    #pragma unroll
    for (int it = 0; it < 4; ++it) {
        int idx = tid + it * 256;
        s += edges[b * 1024 + idx] * (g_eint[b * 1024 + idx] + bias_i);
    }
    if (tid < 32) s += g_erow[b * 32 + tid] + t3b[0];

    __shared__ float red[256];
    red[tid] = s;
    __syncthreads();
    for (int o = 128; o > 0; o >>= 1) {
        if (tid < o) red[tid] += red[tid + o];
        __syncthreads();
    }
    if (tid == 0) out[b] = red[0];
}

// ---------------------------------------------------------------------------
extern "C" void kernel_launch(void* const* d_in, const int* in_sizes, int n_in,
                              void* d_out, int out_size)
{
    const float* x   = (const float*)d_in[0];
    const float* edg = (const float*)d_in[1];
    const float* t1w = (const float*)d_in[2];
    const float* t1b = (const float*)d_in[3];
    const float* t2w = (const float*)d_in[4];
    const float* t2b = (const float*)d_in[5];
    const float* t3w = (const float*)d_in[6];
    const float* t3b = (const float*)d_in[7];
    const float* i1w = (const float*)d_in[8];
    const float* i1b = (const float*)d_in[9];
    const float* i2w = (const float*)d_in[10];
    const float* i2b = (const float*)d_in[11];
    const float* i3w = (const float*)d_in[12];
    const float* i3b = (const float*)d_in[13];
    float* out = (float*)d_out;

    cudaFuncSetAttribute(tensor_stage_kernel,
                         cudaFuncAttributeMaxDynamicSharedMemorySize, TS_SMEM);
    cudaFuncSetAttribute(stage1_mma_kernel,
                         cudaFuncAttributeMaxDynamicSharedMemorySize, TS_SMEM);

    dim3 gp(32, 32, 2);
    prep_transpose<<<gp, dim3(32, 32)>>>(t2w, i2w);

    convert_x_kernel<<<4096, 128>>>(x);
    convert_w1_kernel<<<dim3(96, 13), dim3(32, 32)>>>(t1w, i1w);

    stage1_mma_kernel<<<dim3(32, 24), 128, TS_SMEM>>>(t1b, i1b);

    tensor_stage_kernel<<<8448, 128, TS_SMEM>>>(t2b, t3w, i2b, i3w);

    finalize_kernel<<<128, 256>>>(edg, t3b, i3b, out);
}

// round 16
// speedup vs baseline: 1.0013x; 1.0013x over previous
#include <cuda_runtime.h>
#include <cuda_fp16.h>
#include <cstdint>

// ===========================================================================
// Model_86011015070455 — R16: R15 with the prep_weights grid-guard bug fixed
//   (W2 path must reject blockIdx.x >= 32; R15 read 8MB past the input).
//   Mainloop = R13 (4-stage ring, dual sync — best measured config).
// ===========================================================================

__device__ __forceinline__ uint32_t smem_u32(const void* p) {
    uint32_t a;
    asm("{ .reg .u64 t; cvta.to.shared.u64 t, %1; cvt.u32.u64 %0, t; }" : "=r"(a) : "l"(p));
    return a;
}
__device__ __forceinline__ void ldsm4(uint32_t& r0, uint32_t& r1, uint32_t& r2, uint32_t& r3,
                                      uint32_t addr) {
    asm volatile("ldmatrix.sync.aligned.m8n8.x4.shared.b16 {%0,%1,%2,%3}, [%4];"
                 : "=r"(r0), "=r"(r1), "=r"(r2), "=r"(r3) : "r"(addr));
}
__device__ __forceinline__ void mma16816(float* d, const uint32_t* a, const uint32_t* b) {
    asm volatile("mma.sync.aligned.m16n8k16.row.col.f32.f16.f16.f32 "
                 "{%0,%1,%2,%3}, {%4,%5,%6,%7}, {%8,%9}, {%0,%1,%2,%3};"
                 : "+f"(d[0]), "+f"(d[1]), "+f"(d[2]), "+f"(d[3])
                 : "r"(a[0]), "r"(a[1]), "r"(a[2]), "r"(a[3]), "r"(b[0]), "r"(b[1]));
}
__device__ __forceinline__ void cp16(uint32_t dst, const void* src) {
    asm volatile("cp.async.cg.shared.global [%0], [%1], 16;"
                 :: "r"(dst), "l"(__cvta_generic_to_global(src)));
}
#define CP_COMMIT() asm volatile("cp.async.commit_group;")
#define CP_WAIT2()  asm volatile("cp.async.wait_group 2;")
#define CP_WAIT0()  asm volatile("cp.async.wait_group 0;")
#define SWZ64(o) ((o) ^ (((o) >> 3) & 0x30))

__device__ __forceinline__ uint32_t packh2(__half a, __half b) {
    __half2 t = __halves2half2(a, b);
    return *(uint32_t*)&t;
}
__device__ __forceinline__ uint32_t haddrelu2(uint32_t a, uint32_t b) {
    __half2 s = __hadd2(*(__half2*)&a, *(__half2*)&b);
    s = __hmax2(s, __float2half2_rn(0.f));
    return *(uint32_t*)&s;
}

// ------------------------------------------------------------- device scratch
__device__ __half g_A1h[4096 * 1024];
__device__ __half g_B1h[4096 * 1024];
__device__ __half g_T1h[4096 * 1024];
__device__ float  g_erow[4096];
__device__ float  g_eint[131072];
__device__ __half g_T2T[1024 * 1024];
__device__ __half g_I2T[1024 * 1024];
__device__ __half g_Xh[4096 * 416];
__device__ __half g_W1T[3072 * 416];

// ---------------- fused prep: W2 transposes (z=0,1) + W1 transpose (z=2) ----
__global__ void prep_weights_kernel(const float* __restrict__ t2w,
                                    const float* __restrict__ i2w,
                                    const float* __restrict__ t1w,
                                    const float* __restrict__ i1w) {
    __shared__ float tile[32][33];
    const int z = blockIdx.z;
    if (z < 2) {
        // W2 transpose: 1024x1024, needs bx<32 AND by<32
        if (blockIdx.x >= 32 || blockIdx.y >= 32) return;
        const float* src = z ? i2w : t2w;
        __half* dst = z ? g_I2T : g_T2T;
        int k = blockIdx.y * 32 + threadIdx.y;
        int n = blockIdx.x * 32 + threadIdx.x;
        tile[threadIdx.y][threadIdx.x] = src[k * 1024 + n];
        __syncthreads();
        float v = tile[threadIdx.x][threadIdx.y];
        int nn = blockIdx.x * 32 + threadIdx.y;
        int kk = blockIdx.y * 32 + threadIdx.x;
        dst[nn * 1024 + kk] = __float2half_rn(v);
    } else {
        // W1 transpose: 96 x 13 blocks
        if (blockIdx.x >= 96 || blockIdx.y >= 13) return;
        int n = blockIdx.x * 32 + threadIdx.x;
        int k = blockIdx.y * 32 + threadIdx.y;
        float v = 0.f;
        if (k < 400) {
            int seg = n >> 10, nc = n & 1023;
            v = (seg == 0) ? t1w[k * 1024 + nc]
              : (seg == 1) ? i1w[k * 1024 + nc]
                           : i1w[(k + 400) * 1024 + nc];
        }
        tile[threadIdx.y][threadIdx.x] = v;
        __syncthreads();
        int nn = blockIdx.x * 32 + threadIdx.y;
        int kk = blockIdx.y * 32 + threadIdx.x;
        g_W1T[(size_t)nn * 416 + kk] = __float2half_rn(tile[threadIdx.x][threadIdx.y]);
    }
}

// ------------- prep: x rows -> fp16 (K padded to 416) + zero-init outputs ---
__global__ void convert_x_kernel(const float* __restrict__ x) {
    const int gid = blockIdx.x * 128 + threadIdx.x;
    if (gid < 131072) g_eint[gid] = 0.f;
    if (gid < 4096)   g_erow[gid] = 0.f;
    const int row = blockIdx.x;
    const int t = threadIdx.x;
    if (t >= 104) return;
    const int k = t * 4;
    uint2 out;
    if (k < 400) {
        float4 v = *(const float4*)(x + (size_t)row * 400 + k);
        out = make_uint2(packh2(__float2half_rn(v.x), __float2half_rn(v.y)),
                         packh2(__float2half_rn(v.z), __float2half_rn(v.w)));
    } else {
        out = make_uint2(0u, 0u);
    }
    *(uint2*)&g_Xh[(size_t)row * 416 + k] = out;
}

// --------------------------------------------- shared GEMM tile constants ---
static constexpr uint32_t TB_A = 0;
static constexpr uint32_t TB_B = 8 * 1024;
static constexpr uint32_t TB_STAGE = 16 * 1024;
static constexpr int NSTAGE = 4;
static constexpr uint32_t TS_SMEM = NSTAGE * TB_STAGE + 1024 + 1024;

// ------------------------------------- stage1 GEMM (HMMA): X @ W1 -> 3 segs -
static constexpr int NCH1 = 13;

__global__ __launch_bounds__(128, 2)
void stage1_mma_kernel(const float* __restrict__ t1b, const float* __restrict__ i1b)
{
    extern __shared__ char smem_raw[];
    const uint32_t smem_u = smem_u32(smem_raw);
    const uint32_t base_u = (smem_u + 1023) & ~1023u;
    char* p = smem_raw + (base_u - smem_u);
    float* sb1 = (float*)(p + NSTAGE * TB_STAGE);

    const int tid  = threadIdx.x;
    const int lane = tid & 31;
    const int wid  = tid >> 5;
    const int wm   = wid & 1;
    const int wn   = wid >> 1;
    const int m0   = blockIdx.x * 128;
    const int n0   = blockIdx.y * 128;
    const int seg  = n0 >> 10;

    if (seg == 0)      sb1[tid] = t1b[n0 + tid];
    else if (seg == 1) sb1[tid] = i1b[n0 - 1024 + tid];
    else               sb1[tid] = 0.f;

    auto fillAB = [&](int stage, int k0) {
        const uint32_t sb = base_u + (uint32_t)stage * TB_STAGE;
        #pragma unroll
        for (int t = 0; t < 4; ++t) {
            int idx = tid + t * 128;
            int rl = idx >> 2;
            int cc = idx & 3;
            const __half* src = g_Xh + (size_t)(m0 + rl) * 416 + k0 + cc * 8;
            cp16(sb + TB_A + SWZ64((uint32_t)(rl * 64 + cc * 16)), src);
        }
        #pragma unroll
        for (int t = 0; t < 4; ++t) {
            int idx = tid + t * 128;
            int rl = idx >> 2;
            int cc = idx & 3;
            const __half* src = g_W1T + (size_t)(n0 + rl) * 416 + k0 + cc * 8;
            cp16(sb + TB_B + SWZ64((uint32_t)(rl * 64 + cc * 16)), src);
        }
    };

    uint32_t aoff[4], boff[4];
    #pragma unroll
    for (int mf = 0; mf < 4; ++mf)
        aoff[mf] = (uint32_t)((wm * 64 + mf * 16 + (lane & 15)) * 64 + (lane >> 4) * 16);
    #pragma unroll
    for (int nf2 = 0; nf2 < 4; ++nf2)
        boff[nf2] = (uint32_t)((wn * 64 + nf2 * 16 + (lane & 7) + ((lane & 16) ? 8 : 0)) * 64
                               + ((lane >> 3) & 1) * 16);

    float acc[4][8][4];
    #pragma unroll
    for (int mf = 0; mf < 4; ++mf)
        #pragma unroll
        for (int nf = 0; nf < 8; ++nf)
            #pragma unroll
            for (int q = 0; q < 4; ++q) acc[mf][nf][q] = 0.f;

    auto compute = [&](int stage) {
        const uint32_t sb = base_u + (uint32_t)stage * TB_STAGE;
        #pragma unroll
        for (int kf = 0; kf < 2; ++kf) {
            const uint32_t kadd = kf * 32;
            uint32_t ah[4][4], bf[8][2];
            #pragma unroll
            for (int mf = 0; mf < 4; ++mf) {
                uint32_t sw = SWZ64(aoff[mf] + kadd);
                ldsm4(ah[mf][0], ah[mf][1], ah[mf][2], ah[mf][3], sb + TB_A + sw);
            }
            #pragma unroll
            for (int nf2 = 0; nf2 < 4; ++nf2) {
                uint32_t sw = SWZ64(boff[nf2] + kadd);
                ldsm4(bf[nf2 * 2][0], bf[nf2 * 2][1],
                      bf[nf2 * 2 + 1][0], bf[nf2 * 2 + 1][1], sb + TB_B + sw);
            }
            #pragma unroll
            for (int mf = 0; mf < 4; ++mf)
                #pragma unroll
                for (int nf = 0; nf < 8; ++nf)
                    mma16816(acc[mf][nf], ah[mf], bf[nf]);
        }
    };

    fillAB(0, 0);  CP_COMMIT();
    fillAB(1, 32); CP_COMMIT();
    fillAB(2, 64); CP_COMMIT();

    #pragma unroll 1
    for (int c = 0; c < NCH1; ++c) {
        if (c + 3 < NCH1) {
            fillAB((c + 3) & 3, (c + 3) * 32); CP_COMMIT();
            CP_WAIT2();
        } else {
            CP_WAIT0();
        }
        __syncthreads();
        compute(c & 3);
        __syncthreads();
    }

    const int colBase = n0 & 1023;
    #pragma unroll
    for (int mf = 0; mf < 4; ++mf) {
        #pragma unroll
        for (int h = 0; h < 2; ++h) {
            const int m = m0 + wm * 64 + mf * 16 + (lane >> 2) + h * 8;
            #pragma unroll
            for (int nf = 0; nf < 8; ++nf) {
                const int nl = wn * 64 + nf * 8 + 2 * (lane & 3);
                float d0 = acc[mf][nf][h * 2 + 0] + sb1[nl];
                float d1 = acc[mf][nf][h * 2 + 1] + sb1[nl + 1];
                const size_t o = (size_t)m * 1024 + colBase + nl;
                if (seg == 0) {
                    d0 = fmaxf(d0, 0.f); d1 = fmaxf(d1, 0.f);
                    *(uint32_t*)&g_T1h[o] = packh2(__float2half_rn(d0), __float2half_rn(d1));
                } else if (seg == 1) {
                    *(uint32_t*)&g_A1h[o] = packh2(__float2half_rn(d0), __float2half_rn(d1));
                } else {
                    *(uint32_t*)&g_B1h[o] = packh2(__float2half_rn(d0), __float2half_rn(d1));
                }
            }
        }
    }
}

// --------------------------------------------- unified tensor stage (HMMA)
// R13 mainloop (4-stage ring, dual sync). bx<8192: interaction (A built on
// the fly from L2-resident A1h/B1h); bx>=8192: traj (A cp.async from T1h).
static constexpr int NCH = 32;

__global__ __launch_bounds__(128, 2)
void tensor_stage_kernel(const float* __restrict__ t2b, const float* __restrict__ t3w,
                         const float* __restrict__ i2b, const float* __restrict__ i3w)
{
    extern __shared__ char smem_raw[];
    const uint32_t smem_u = smem_u32(smem_raw);
    const uint32_t base_u = (smem_u + 1023) & ~1023u;
    char* p = smem_raw + (base_u - smem_u);

    float* sb2 = (float*)(p + NSTAGE * TB_STAGE);
    float* sw3 = sb2 + 128;

    const int tid  = threadIdx.x;
    const int lane = tid & 31;
    const int wid  = tid >> 5;
    const int wm   = wid & 1;
    const int wn   = wid >> 1;

    const bool traj = (blockIdx.x >= 8192);
    const int idx   = traj ? (blockIdx.x - 8192) : blockIdx.x;
    const int m0    = (idx >> 3) * 128;
    const int n0    = (idx & 7) * 128;

    const __half* WT  = traj ? g_T2T : g_I2T;
    const float*  b2g = traj ? t2b : i2b;
    const float*  w3g = traj ? t3w : i3w;
    float* eout       = traj ? g_erow : g_eint;

    sb2[tid] = b2g[n0 + tid];
    sw3[tid] = w3g[n0 + tid];

    const int rowA_base = (m0 >> 10) * 32 + ((m0 >> 5) & 31);
    const int rowB_base = (m0 >> 10) * 32;

    auto fillB = [&](int stage, int k0) {
        const uint32_t sb = base_u + (uint32_t)stage * TB_STAGE;
        #pragma unroll
        for (int t = 0; t < 4; ++t) {
            int idx2 = tid + t * 128;
            int rl = idx2 >> 2;
            int cc = idx2 & 3;
            const __half* src = WT + (size_t)(n0 + rl) * 1024 + k0 + cc * 8;
            cp16(sb + TB_B + SWZ64((uint32_t)(rl * 64 + cc * 16)), src);
        }
    };
    auto fillA_traj = [&](int stage, int k0) {
        const uint32_t sb = base_u + (uint32_t)stage * TB_STAGE;
        #pragma unroll
        for (int t = 0; t < 4; ++t) {
            int idx2 = tid + t * 128;
            int rl = idx2 >> 2;
            int cc = idx2 & 3;
            const __half* src = g_T1h + (size_t)(m0 + rl) * 1024 + k0 + cc * 8;
            cp16(sb + TB_A + SWZ64((uint32_t)(rl * 64 + cc * 16)), src);
        }
    };

    uint4 va[4], vb[4];
    auto ldA_int = [&](int k0) {
        #pragma unroll
        for (int t = 0; t < 4; ++t) {
            int idx2 = tid + t * 128;
            int rl = idx2 >> 2;
            int cc = idx2 & 3;
            int ra = rowA_base + (rl >> 5);
            int rb = rowB_base + (rl & 31);
            va[t] = *(const uint4*)&g_A1h[(size_t)ra * 1024 + k0 + cc * 8];
            vb[t] = *(const uint4*)&g_B1h[(size_t)rb * 1024 + k0 + cc * 8];
        }
    };
    auto stA_int = [&](int stage) {
        #pragma unroll
        for (int t = 0; t < 4; ++t) {
            int idx2 = tid + t * 128;
            int rl = idx2 >> 2;
            int cc = idx2 & 3;
            uint4 o;
            o.x = haddrelu2(va[t].x, vb[t].x);
            o.y = haddrelu2(va[t].y, vb[t].y);
            o.z = haddrelu2(va[t].z, vb[t].z);
            o.w = haddrelu2(va[t].w, vb[t].w);
            *(uint4*)(p + (uint32_t)stage * TB_STAGE + TB_A
                      + SWZ64((uint32_t)(rl * 64 + cc * 16))) = o;
        }
    };

    uint32_t aoff[4], boff[4];
    #pragma unroll
    for (int mf = 0; mf < 4; ++mf)
        aoff[mf] = (uint32_t)((wm * 64 + mf * 16 + (lane & 15)) * 64 + (lane >> 4) * 16);
    #pragma unroll
    for (int nf2 = 0; nf2 < 4; ++nf2)
        boff[nf2] = (uint32_t)((wn * 64 + nf2 * 16 + (lane & 7) + ((lane & 16) ? 8 : 0)) * 64
                               + ((lane >> 3) & 1) * 16);

    float acc[4][8][4];
    #pragma unroll
    for (int mf = 0; mf < 4; ++mf)
        #pragma unroll
        for (int nf = 0; nf < 8; ++nf)
            #pragma unroll
            for (int q = 0; q < 4; ++q) acc[mf][nf][q] = 0.f;

    auto compute = [&](int stage) {
        const uint32_t sb = base_u + (uint32_t)stage * TB_STAGE;
        #pragma unroll
        for (int kf = 0; kf < 2; ++kf) {
            const uint32_t kadd = kf * 32;
            uint32_t ah[4][4], bf[8][2];
            #pragma unroll
            for (int mf = 0; mf < 4; ++mf) {
                uint32_t sw = SWZ64(aoff[mf] + kadd);
                ldsm4(ah[mf][0], ah[mf][1], ah[mf][2], ah[mf][3], sb + TB_A + sw);
            }
            #pragma unroll
            for (int nf2 = 0; nf2 < 4; ++nf2) {
                uint32_t sw = SWZ64(boff[nf2] + kadd);
                ldsm4(bf[nf2 * 2][0], bf[nf2 * 2][1],
                      bf[nf2 * 2 + 1][0], bf[nf2 * 2 + 1][1], sb + TB_B + sw);
            }
            #pragma unroll
            for (int mf = 0; mf < 4; ++mf)
                #pragma unroll
                for (int nf = 0; nf < 8; ++nf)
                    mma16816(acc[mf][nf], ah[mf], bf[nf]);
        }
    };

    // ---- prologue ----
    fillB(0, 0);  if (traj) fillA_traj(0, 0);  CP_COMMIT();
    fillB(1, 32); if (traj) fillA_traj(1, 32); CP_COMMIT();
    fillB(2, 64); if (traj) fillA_traj(2, 64); CP_COMMIT();
    if (!traj) { ldA_int(0); stA_int(0); }

    #pragma unroll 1
    for (int c = 0; c < NCH; ++c) {
        if (c + 3 < NCH) {
            fillB((c + 3) & 3, (c + 3) * 32);
            if (traj) fillA_traj((c + 3) & 3, (c + 3) * 32);
            CP_COMMIT();
        }
        if (!traj && c + 1 < NCH) ldA_int((c + 1) * 32);
        if (c + 3 < NCH) CP_WAIT2(); else CP_WAIT0();
        __syncthreads();
        compute(c & 3);
        if (!traj && c + 1 < NCH) stA_int((c + 1) & 3);
        __syncthreads();
    }

    // ---- epilogue: fused layer-3  e_m += sum_n w3[n]*relu(D+b2[n]) ----
    #pragma unroll
    for (int mf = 0; mf < 4; ++mf) {
        #pragma unroll
        for (int h = 0; h < 2; ++h) {
            float s = 0.f;
            #pragma unroll
            for (int nf = 0; nf < 8; ++nf) {
                int nl = wn * 64 + nf * 8 + 2 * (lane & 3);
                float d0 = acc[mf][nf][h * 2 + 0];
                float d1 = acc[mf][nf][h * 2 + 1];
                s += fmaxf(d0 + sb2[nl], 0.f) * sw3[nl]
                   + fmaxf(d1 + sb2[nl + 1], 0.f) * sw3[nl + 1];
            }
            s += __shfl_xor_sync(0xffffffffu, s, 1);
            s += __shfl_xor_sync(0xffffffffu, s, 2);
            if ((lane & 3) == 0) {
                int m = m0 + wm * 64 + mf * 16 + (lane >> 2) + h * 8;
                atomicAdd(&eout[m], s);
            }
        }
    }
}

// ------------------------------------------------------------------ finalize
__global__ void finalize_kernel(const float* __restrict__ edges,
                                const float* __restrict__ t3b,
                                const float* __restrict__ i3b,
                                float* __restrict__ out)
{
    const int b = blockIdx.x;
    const int tid = threadIdx.x;
    const float bias_i = i3b[0];

    float s = 0.f;
    #pragma unroll
    for (int it = 0; it < 4; ++it) {
        int idx = tid + it * 256;
        s += edges[b * 1024 + idx] * (g_eint[b * 1024 + idx] + bias_i);
    }
    if (tid < 32) s += g_erow[b * 32 + tid] + t3b[0];

    __shared__ float red[256];
    red[tid] = s;
    __syncthreads();
    for (int o = 128; o > 0; o >>= 1) {
        if (tid < o) red[tid] += red[tid + o];
        __syncthreads();
    }
    if (tid == 0) out[b] = red[0];
}

// ---------------------------------------------------------------------------
extern "C" void kernel_launch(void* const* d_in, const int* in_sizes, int n_in,
                              void* d_out, int out_size)
{
    const float* x   = (const float*)d_in[0];
    const float* edg = (const float*)d_in[1];
    const float* t1w = (const float*)d_in[2];
    const float* t1b = (const float*)d_in[3];
    const float* t2w = (const float*)d_in[4];
    const float* t2b = (const float*)d_in[5];
    const float* t3w = (const float*)d_in[6];
    const float* t3b = (const float*)d_in[7];
    const float* i1w = (const float*)d_in[8];
    const float* i1b = (const float*)d_in[9];
    const float* i2w = (const float*)d_in[10];
    const float* i2b = (const float*)d_in[11];
    const float* i3w = (const float*)d_in[12];
    const float* i3b = (const float*)d_in[13];
    float* out = (float*)d_out;

    cudaFuncSetAttribute(tensor_stage_kernel,
                         cudaFuncAttributeMaxDynamicSharedMemorySize, TS_SMEM);
    cudaFuncSetAttribute(stage1_mma_kernel,
                         cudaFuncAttributeMaxDynamicSharedMemorySize, TS_SMEM);

    dim3 gp(96, 32, 3);   // z=0,1: W2 transposes (use bx<32); z=2: W1 (96x13)
    prep_weights_kernel<<<gp, dim3(32, 32)>>>(t2w, i2w, t1w, i1w);

    convert_x_kernel<<<4096, 128>>>(x);

    stage1_mma_kernel<<<dim3(32, 24), 128, TS_SMEM>>>(t1b, i1b);

    tensor_stage_kernel<<<8448, 128, TS_SMEM>>>(t2b, t3w, i2b, i3w);

    finalize_kernel<<<128, 256>>>(edg, t3b, i3b, out);
}